// round 11
// baseline (speedup 1.0000x reference)
#include <cuda_runtime.h>
#include <cstdint>

// Problem constants
constexpr int Bb   = 32;
constexpr int Ll   = 32768;
constexpr int Hh   = 32;      // == warp size: lane = head
constexpr int N2   = 8;       // complex modes per head
constexpr int CND  = 4;
constexpr int LC   = 128;     // chunk length
constexpr int CH   = Ll / LC; // 256 chunks
constexpr int NG   = N2 / 2;  // 4 packed state groups

// ---------------- scratch (device globals; no allocation) ----------------
__device__ float2 g_state[(size_t)Bb * CH * N2 * Hh];          // 16 MB: end-states then carries (in-place)
__device__ float  g_wr[Hh * N2], g_wi[Hh * N2];
__device__ float  g_c2r[Hh * N2], g_c2i[Hh * N2];              // 2*Ct (pre-doubled)
__device__ float  g_wLr[Hh * N2], g_wLi[Hh * N2];              // w^LC
__device__ float  g_gamma[Bb * Hh], g_beta[Bb * Hh], g_gd[Bb * Hh];

// ---------------- packed f32x2 helpers ----------------
__device__ __forceinline__ unsigned long long pk(float lo, float hi) {
    unsigned long long r;
    asm("mov.b64 %0, {%1, %2};" : "=l"(r) : "f"(lo), "f"(hi));
    return r;
}
__device__ __forceinline__ void upk(unsigned long long v, float& lo, float& hi) {
    asm("mov.b64 {%0, %1}, %2;" : "=f"(lo), "=f"(hi) : "l"(v));
}
__device__ __forceinline__ unsigned long long fma2(unsigned long long a, unsigned long long b,
                                                   unsigned long long c) {
    unsigned long long d;
    asm("fma.rn.f32x2 %0, %1, %2, %3;" : "=l"(d) : "l"(a), "l"(b), "l"(c));
    return d;
}
__device__ __forceinline__ unsigned long long mul2(unsigned long long a, unsigned long long b) {
    unsigned long long d;
    asm("mul.rn.f32x2 %0, %1, %2;" : "=l"(d) : "l"(a), "l"(b));
    return d;
}

// ---------------- precompute: per-(h,n) SSM constants ----------------
__global__ void k_const(const float* __restrict__ log_dt,
                        const float* __restrict__ C_re,
                        const float* __restrict__ C_im,
                        const float* __restrict__ log_A_real,
                        const float* __restrict__ A_imag) {
    int t = threadIdx.x;
    if (t >= Hh * N2) return;
    int h = t / N2;
    double dt  = exp((double)log_dt[h]);
    double Are = -exp((double)log_A_real[t]);
    double Aim = (double)A_imag[t];
    double ar = Are * dt, ai = Aim * dt;
    double er = exp(ar);
    double wr = er * cos(ai), wi = er * sin(ai);
    g_wr[t] = (float)wr;
    g_wi[t] = (float)wi;
    // (exp(dtA)-1)/A = (E-1) * conj(A) / |A|^2
    double em1r = wr - 1.0, em1i = wi;
    double den = Are * Are + Aim * Aim;
    double fr = (em1r * Are + em1i * Aim) / den;
    double fi = (em1i * Are - em1r * Aim) / den;
    double cr = (double)C_re[t], ci = (double)C_im[t];
    double Ctr = cr * fr - ci * fi;
    double Cti = cr * fi + ci * fr;
    g_c2r[t] = (float)(2.0 * Ctr);
    g_c2i[t] = (float)(2.0 * Cti);
    // w^LC computed directly (no iterated drift)
    double eL = exp(ar * (double)LC);
    g_wLr[t] = (float)(eL * cos(ai * (double)LC));
    g_wLi[t] = (float)(eL * sin(ai * (double)LC));
}

// ---------------- precompute: FiLM gamma/beta per (b,h) ----------------
__global__ void k_film(const float* __restrict__ cond,
                       const float* __restrict__ film_W,
                       const float* __restrict__ film_b,
                       const float* __restrict__ D) {
    int t = blockIdx.x * blockDim.x + threadIdx.x;
    if (t >= Bb * Hh) return;
    int b = t / Hh, h = t % Hh;
    float g = 0.f, be = film_b[Hh + h];
    float gb0 = film_b[h];
#pragma unroll
    for (int c = 0; c < CND; c++) {
        float cv = cond[b * CND + c];
        g  = fmaf(cv, film_W[c * (2 * Hh) + h], g);
        be = fmaf(cv, film_W[c * (2 * Hh) + Hh + h], be);
    }
    g += gb0 * 0.f;  // film_b[:H] is part of gamma in reference: gb[:, :H] includes film_b
    g += film_b[h];
    g_gamma[t] = g;
    g_beta[t]  = be;
    g_gd[t]    = g * D[h];
}

// ---------------- phase 1: per-chunk end states (zero init) ----------------
__global__ void __launch_bounds__(256) k_phase1(const float* __restrict__ x) {
    int gt   = blockIdx.x * blockDim.x + threadIdx.x;
    int wid  = gt >> 5;           // 0 .. B*CH-1
    int lane = threadIdx.x & 31;  // head
    int b = wid >> 8;             // CH = 256
    int c = wid & 255;

    int base = lane * N2;
    unsigned long long wr[NG], wi[NG], nwi[NG], sr[NG], si[NG];
#pragma unroll
    for (int g = 0; g < NG; g++) {
        float w0r = g_wr[base + 2 * g], w1r = g_wr[base + 2 * g + 1];
        float w0i = g_wi[base + 2 * g], w1i = g_wi[base + 2 * g + 1];
        wr[g]  = pk(w0r, w1r);
        wi[g]  = pk(w0i, w1i);
        nwi[g] = pk(-w0i, -w1i);
        sr[g]  = pk(0.f, 0.f);
        si[g]  = pk(0.f, 0.f);
    }

    const float* up = x + ((size_t)b * Ll + (size_t)c * LC) * Hh + lane;
#pragma unroll 4
    for (int j = 0; j < LC; j++) {
        float u = __ldg(up);
        up += Hh;
        unsigned long long uu = pk(u, u);
#pragma unroll
        for (int g = 0; g < NG; g++) {
            unsigned long long tr = fma2(wr[g], sr[g], uu);
            tr = fma2(nwi[g], si[g], tr);
            unsigned long long ti = mul2(wr[g], si[g]);
            ti = fma2(wi[g], sr[g], ti);
            sr[g] = tr;
            si[g] = ti;
        }
    }

    float2* st = g_state + ((size_t)wid * N2) * Hh + lane;
#pragma unroll
    for (int g = 0; g < NG; g++) {
        float a0, a1, b0, b1;
        upk(sr[g], a0, a1);
        upk(si[g], b0, b1);
        st[(2 * g) * Hh]     = make_float2(a0, b0);
        st[(2 * g + 1) * Hh] = make_float2(a1, b1);
    }
}

// ---------------- phase 2: carry scan across chunks (in-place) ----------------
__global__ void k_phase2() {
    int t = blockIdx.x * blockDim.x + threadIdx.x;  // 0 .. B*N2*H-1
    if (t >= Bb * N2 * Hh) return;
    int h = t & 31;
    int n = (t >> 5) & (N2 - 1);
    int b = t >> 8;
    float wLr = g_wLr[h * N2 + n], wLi = g_wLi[h * N2 + n];
    float cr = 0.f, ci = 0.f;
    for (int c = 0; c < CH; c++) {
        size_t idx = (((size_t)(b * CH + c) * N2 + n) * Hh) + h;
        float2 e = g_state[idx];
        g_state[idx] = make_float2(cr, ci);  // carry-in for chunk c
        float ncr = fmaf(wLr, cr, fmaf(-wLi, ci, e.x));
        float nci = fmaf(wLr, ci, fmaf(wLi, cr, e.y));
        cr = ncr;
        ci = nci;
    }
}

// ---------------- phase 3: recurrence with carry + skip + FiLM + GELU ----------------
__global__ void __launch_bounds__(256) k_phase3(const float* __restrict__ x,
                                                float* __restrict__ out) {
    int gt   = blockIdx.x * blockDim.x + threadIdx.x;
    int wid  = gt >> 5;
    int lane = threadIdx.x & 31;
    int b = wid >> 8;
    int c = wid & 255;

    int base = lane * N2;
    int bh = b * Hh + lane;
    float gamma = g_gamma[bh];
    float beta  = g_beta[bh];
    float gd    = g_gd[bh];

    unsigned long long wr[NG], wi[NG], nwi[NG], c2r[NG], nc2i[NG], sr[NG], si[NG];
    const float2* st = g_state + ((size_t)wid * N2) * Hh + lane;
#pragma unroll
    for (int g = 0; g < NG; g++) {
        float w0r = g_wr[base + 2 * g], w1r = g_wr[base + 2 * g + 1];
        float w0i = g_wi[base + 2 * g], w1i = g_wi[base + 2 * g + 1];
        wr[g]  = pk(w0r, w1r);
        wi[g]  = pk(w0i, w1i);
        nwi[g] = pk(-w0i, -w1i);
        // fold gamma into the (pre-doubled) output coefficients
        c2r[g]  = pk(gamma * g_c2r[base + 2 * g], gamma * g_c2r[base + 2 * g + 1]);
        nc2i[g] = pk(-gamma * g_c2i[base + 2 * g], -gamma * g_c2i[base + 2 * g + 1]);
        float2 v0 = st[(2 * g) * Hh];
        float2 v1 = st[(2 * g + 1) * Hh];
        sr[g] = pk(v0.x, v1.x);
        si[g] = pk(v0.y, v1.y);
    }

    size_t off = ((size_t)b * Ll + (size_t)c * LC) * Hh + lane;
    const float* up = x + off;
    float* op = out + off;
    const float k2 = 1.5957691216057308f;  // 2*sqrt(2/pi)

#pragma unroll 4
    for (int j = 0; j < LC; j++) {
        float u = __ldg(up);
        up += Hh;
        unsigned long long uu = pk(u, u);
        unsigned long long acc = pk(fmaf(gd, u, beta), 0.f);
#pragma unroll
        for (int g = 0; g < NG; g++) {
            unsigned long long tr = fma2(wr[g], sr[g], uu);
            tr = fma2(nwi[g], si[g], tr);
            unsigned long long ti = mul2(wr[g], si[g]);
            ti = fma2(wi[g], sr[g], ti);
            sr[g] = tr;
            si[g] = ti;
            acc = fma2(c2r[g], tr, acc);
            acc = fma2(nc2i[g], ti, acc);
        }
        float ylo, yhi;
        upk(acc, ylo, yhi);
        float y = ylo + yhi;  // gamma*(conv + D*u) + beta

        // gelu (tanh approx, matching jax.nn.gelu default): tanh via expf
        float yy = y * y;
        float inner = fmaf(0.044715f * yy, y, y);
        float e = __expf(k2 * inner);
        float r = __fdividef(2.0f, e + 1.0f);
        float g_out = fmaf(-0.5f * y, r, y);  // 0.5*y*(1+tanh) = y - 0.5*y*(1-tanh)

        *op = g_out;
        op += Hh;
    }
}

// ---------------- launch ----------------
extern "C" void kernel_launch(void* const* d_in, const int* in_sizes, int n_in,
                              void* d_out, int out_size) {
    const float* x          = (const float*)d_in[0];
    const float* cond       = (const float*)d_in[1];
    const float* log_dt     = (const float*)d_in[2];
    const float* C_re       = (const float*)d_in[3];
    const float* C_im       = (const float*)d_in[4];
    const float* log_A_real = (const float*)d_in[5];
    const float* A_imag     = (const float*)d_in[6];
    const float* D          = (const float*)d_in[7];
    const float* film_W     = (const float*)d_in[8];
    const float* film_b     = (const float*)d_in[9];
    float* out = (float*)d_out;

    k_const<<<1, 256>>>(log_dt, C_re, C_im, log_A_real, A_imag);
    k_film<<<(Bb * Hh + 255) / 256, 256>>>(cond, film_W, film_b, D);

    int total_warps = Bb * CH;               // 8192
    int blocks = total_warps * 32 / 256;     // 1024
    k_phase1<<<blocks, 256>>>(x);
    k_phase2<<<(Bb * N2 * Hh + 255) / 256, 256>>>();
    k_phase3<<<blocks, 256>>>(x, out);
}